// round 9
// baseline (speedup 1.0000x reference)
#include <cuda_runtime.h>
#include <cstdint>

// D-FPS (B=8, N=32768, npoint=2048) + gather xyz -> out (B,3,2048) fp32.
//
// One 8-CTA cluster per batch (64 CTAs, 512 threads). Each thread owns 8
// points packed f32x2 in registers; running-min temps in registers.
// Per iteration (NO cluster barrier in the loop):
//   1. packed add/mul.rn.f32x2 distance update (per-lane .rn => bit-exact),
//      in-loop argmax (ascending scan => first-occurrence ties)
//   2. warp argmax via redux.sync (float bits of v>=0 are u32-monotone),
//      min-index tie-break == jnp.argmax
//   3. bar.sync; warp0 reduces 16 warp candidates; lane0 stores the CTA
//      candidate {key, x,y,z} to CTA0's smem (mapa + st.shared::cluster) and
//      releases cand_tag[rank]=j (st.release.cluster). Tags are monotone.
//   4. CTA0's warp0: volatile-polls the 8 cand tags, fence.acq_rel.cluster,
//      every lane picks max key (u64, idx-complement tie-break), lanes 0..7
//      broadcast ONLY the winner coords (16B) to all CTAs + release
//      win_tag=j; lane0 writes the output sample.
//   5. All other warps volatile-poll their local win_tag==j, fence, one
//      LDS.128 -> winner coords. (Per-thread 8-way key pick is eliminated.)
// Reuse safety without double buffering: candidates j+1 are stored only
// after the producer CTA passed sync A(j+1), which requires all its threads
// to have consumed winner j; winner j+1 is stored only after all candidates
// j+1 arrived. Monotone tags, zero-init + one startup cluster barrier.

constexpr int BATCH   = 8;
constexpr int NPTS    = 32768;
constexpr int NPOINT  = 2048;
constexpr int CLUSTER = 8;
constexpr int T       = 512;
constexpr int PER_CTA = NPTS / CLUSTER;  // 4096
constexpr int P       = PER_CTA / T;     // 8 points / thread
constexpr int NPAIR   = P / 2;           // 4 packed pairs
constexpr int NW      = T / 32;          // 16 warps

__device__ __forceinline__ uint32_t smem_u32(const void* p) {
    uint32_t a;
    asm("{ .reg .u64 t; cvta.to.shared.u64 t, %1; cvt.u32.u64 %0, t; }"
        : "=r"(a) : "l"(p));
    return a;
}

extern __shared__ float s_dyn[];  // sx[4096] | sy[4096] | sz[4096] = 48KB

__global__ __launch_bounds__(T, 1) __cluster_dims__(CLUSTER, 1, 1)
void fps_cluster_kernel(const float* __restrict__ xyz_t, float* __restrict__ out)
{
    const int b = blockIdx.x >> 3;
    uint32_t rank;
    asm("mov.u32 %0, %%cluster_ctarank;" : "=r"(rank));

    const float* __restrict__ xs = xyz_t + (size_t)b * 3 * NPTS;
    const float* __restrict__ ys = xs + NPTS;
    const float* __restrict__ zs = xs + 2 * NPTS;
    float* __restrict__ ob = out + (size_t)b * 3 * NPOINT;

    const int tid = threadIdx.x;
    const int w = tid >> 5, l = tid & 31;
    const int pbase = (int)rank * PER_CTA;

    float* sx = s_dyn;
    float* sy = s_dyn + PER_CTA;
    float* sz = s_dyn + 2 * PER_CTA;

    __shared__ uint32_t s_wv[NW], s_wi[NW];
    // CTA0-only candidate mailbox (exists in every CTA, used in rank 0)
    __shared__ unsigned long long s_ckey[CLUSTER];      // 64B, 16-aligned
    __shared__ float4 s_cco[CLUSTER];
    __shared__ uint32_t s_ctag[CLUSTER];
    // winner mailbox (every CTA)
    __shared__ float4 s_win;
    __shared__ uint32_t s_wtag;

    // ---- load coords: smem table + packed registers ----
    unsigned long long xp[NPAIR], yp[NPAIR], zp[NPAIR];
    float tmp[P];
    {
        float a[P], c[P], d[P];
#pragma unroll
        for (int i = 0; i < P; ++i) {
            const int g = pbase + i * T + tid;
            a[i] = xs[g]; c[i] = ys[g]; d[i] = zs[g];
            sx[i * T + tid] = a[i];
            sy[i * T + tid] = c[i];
            sz[i * T + tid] = d[i];
            tmp[i] = 1e10f;
        }
#pragma unroll
        for (int q = 0; q < NPAIR; ++q) {
            asm("mov.b64 %0, {%1, %2};" : "=l"(xp[q]) : "f"(a[2*q]), "f"(a[2*q+1]));
            asm("mov.b64 %0, {%1, %2};" : "=l"(yp[q]) : "f"(c[2*q]), "f"(c[2*q+1]));
            asm("mov.b64 %0, {%1, %2};" : "=l"(zp[q]) : "f"(d[2*q]), "f"(d[2*q+1]));
        }
    }
    if (tid < CLUSTER) s_ctag[tid] = 0u;
    if (tid == CLUSTER) s_wtag = 0u;

    // tags must be zero cluster-wide before any remote release-store
    asm volatile("barrier.cluster.arrive.aligned;" ::: "memory");
    asm volatile("barrier.cluster.wait.aligned;" ::: "memory");

    float lx = __ldg(xs), ly = __ldg(ys), lz = __ldg(zs);  // idx[0] = 0
    if (rank == 0 && tid == 0) {
        ob[0] = lx; ob[NPOINT] = ly; ob[2 * NPOINT] = lz;
    }

    const uint32_t wtag_a = smem_u32(&s_wtag);
    const uint32_t win_a  = smem_u32(&s_win);

    for (int j = 1; j < NPOINT; ++j) {
        // packed negated center (per-lane duplicate)
        unsigned long long nlx2, nly2, nlz2;
        {
            const float nx = -lx, ny = -ly, nz = -lz;
            asm("mov.b64 %0, {%1, %1};" : "=l"(nlx2) : "f"(nx));
            asm("mov.b64 %0, {%1, %1};" : "=l"(nly2) : "f"(ny));
            asm("mov.b64 %0, {%1, %1};" : "=l"(nlz2) : "f"(nz));
        }

        float bv = -1.0f;
        int   bs = 0;
#pragma unroll
        for (int q = 0; q < NPAIR; ++q) {
            unsigned long long dx, dy, dz, qx, qy, qz, s01, acc;
            asm("add.rn.f32x2 %0, %1, %2;" : "=l"(dx) : "l"(xp[q]), "l"(nlx2));
            asm("add.rn.f32x2 %0, %1, %2;" : "=l"(dy) : "l"(yp[q]), "l"(nly2));
            asm("add.rn.f32x2 %0, %1, %2;" : "=l"(dz) : "l"(zp[q]), "l"(nlz2));
            asm("mul.rn.f32x2 %0, %1, %1;" : "=l"(qx) : "l"(dx));
            asm("mul.rn.f32x2 %0, %1, %1;" : "=l"(qy) : "l"(dy));
            asm("mul.rn.f32x2 %0, %1, %1;" : "=l"(qz) : "l"(dz));
            asm("add.rn.f32x2 %0, %1, %2;" : "=l"(s01) : "l"(qx), "l"(qy));
            asm("add.rn.f32x2 %0, %1, %2;" : "=l"(acc) : "l"(s01), "l"(qz));
            float d0, d1;
            asm("mov.b64 {%0, %1}, %2;" : "=f"(d0), "=f"(d1) : "l"(acc));
            float t0 = fminf(tmp[2*q], d0);     tmp[2*q] = t0;
            if (t0 > bv) { bv = t0; bs = 2*q; }
            float t1 = fminf(tmp[2*q+1], d1);   tmp[2*q+1] = t1;
            if (t1 > bv) { bv = t1; bs = 2*q+1; }
        }
        const uint32_t idx = (uint32_t)(pbase + bs * T + tid);

        // ---- warp argmax via redux (float bits of v>=0 are u32-monotone) ----
        const uint32_t vb   = __float_as_uint(bv);
        const uint32_t vmax = __reduce_max_sync(0xffffffffu, vb);
        const uint32_t imin = __reduce_min_sync(0xffffffffu,
                                   (vb == vmax) ? idx : 0xffffffffu);
        if (l == 0) { s_wv[w] = vmax; s_wi[w] = imin; }
        __syncthreads();   // sync A: warp candidates visible; also anchors the
                           // happens-before chain for mailbox reuse

        if (w == 0) {
            const uint32_t v  = (l < NW) ? s_wv[l] : 0u;
            const uint32_t ii = (l < NW) ? s_wi[l] : 0xffffffffu;
            const uint32_t vm = __reduce_max_sync(0xffffffffu, v);
            const uint32_t im = __reduce_min_sync(0xffffffffu,
                                    (v == vm) ? ii : 0xffffffffu);
            if (l == 0) {
                const int li = (int)im - pbase;          // in own range
                const float cx = sx[li], cy = sy[li], cz = sz[li];  // LDS
                const unsigned long long key =
                    ((unsigned long long)vm << 32) | (uint32_t)(~im);
                unsigned long long xyp;
                asm("mov.b64 %0, {%1, %2};" : "=l"(xyp) : "f"(cx), "f"(cy));
                const uint32_t zb = __float_as_uint(cz);
                const uint32_t ka = smem_u32(&s_ckey[rank]);
                const uint32_t ca = smem_u32(&s_cco[rank]);
                const uint32_t ta = smem_u32(&s_ctag[rank]);
                const int dco = (int)(ca - ka);
                const int dta = (int)(ta - ka);
                uint32_t rk;   // slot[rank] inside CTA0
                asm volatile("mapa.shared::cluster.u32 %0, %1, %2;"
                             : "=r"(rk) : "r"(ka), "r"(0));
                asm volatile("st.shared::cluster.b64 [%0], %1;"
                             :: "r"(rk), "l"(key) : "memory");
                asm volatile("st.shared::cluster.b64 [%0], %1;"
                             :: "r"(rk + dco), "l"(xyp) : "memory");
                asm volatile("st.shared::cluster.b32 [%0+8], %1;"
                             :: "r"(rk + dco), "r"(zb) : "memory");
                asm volatile("st.release.cluster.shared::cluster.u32 [%0], %1;"
                             :: "r"(rk + dta), "r"((uint32_t)j) : "memory");
            }
        }

        if (rank == 0 && w == 0) {
            // ---- reducer warp: wait for all 8 candidates ----
            const uint32_t myta = smem_u32(&s_ctag[l & 7]);
            bool done = (l >= CLUSTER);
            while (!__all_sync(0xffffffffu, done)) {
                if (!done) {
                    uint32_t t;
                    asm volatile("ld.volatile.shared.u32 %0, [%1];"
                                 : "=r"(t) : "r"(myta));
                    done = (t == (uint32_t)j);
                }
            }
            asm volatile("fence.acq_rel.cluster;" ::: "memory");

            // every lane picks max key (broadcast LDS, redundant = no shfl)
            unsigned long long wk = s_ckey[0];
            int wc = 0;
#pragma unroll
            for (int c = 1; c < CLUSTER; ++c) {
                const unsigned long long kk = s_ckey[c];
                if (kk > wk) { wk = kk; wc = c; }
            }
            const float4 co = s_cco[wc];
            lx = co.x; ly = co.y; lz = co.z;

            // lanes 0..7 broadcast winner coords + tag to all CTAs
            if (l < CLUSTER) {
                unsigned long long xyp;
                asm("mov.b64 %0, {%1, %2};" : "=l"(xyp) : "f"(lx), "f"(ly));
                const uint32_t zb = __float_as_uint(lz);
                uint32_t rw, rt;
                asm volatile("mapa.shared::cluster.u32 %0, %1, %2;"
                             : "=r"(rw) : "r"(win_a), "r"(l));
                asm volatile("mapa.shared::cluster.u32 %0, %1, %2;"
                             : "=r"(rt) : "r"(wtag_a), "r"(l));
                asm volatile("st.shared::cluster.b64 [%0], %1;"
                             :: "r"(rw), "l"(xyp) : "memory");
                asm volatile("st.shared::cluster.b32 [%0+8], %1;"
                             :: "r"(rw), "r"(zb) : "memory");
                asm volatile("st.release.cluster.shared::cluster.u32 [%0], %1;"
                             :: "r"(rt), "r"((uint32_t)j) : "memory");
            }
            if (l == 0) {
                ob[j]              = lx;
                ob[NPOINT + j]     = ly;
                ob[2 * NPOINT + j] = lz;
            }
        } else {
            // ---- all other warps: wait for the winner broadcast ----
            uint32_t t;
            do {
                asm volatile("ld.volatile.shared.u32 %0, [%1];"
                             : "=r"(t) : "r"(wtag_a));
            } while (t != (uint32_t)j);
            asm volatile("fence.acq_rel.cluster;" ::: "memory");
            const float4 co = s_win;
            lx = co.x; ly = co.y; lz = co.z;
        }
    }

    // no CTA may exit while peers may still target its smem
    asm volatile("barrier.cluster.arrive.aligned;" ::: "memory");
    asm volatile("barrier.cluster.wait.aligned;" ::: "memory");
}

extern "C" void kernel_launch(void* const* d_in, const int* in_sizes, int n_in,
                              void* d_out, int out_size)
{
    (void)in_sizes; (void)n_in; (void)out_size;
    const float* xyz_t = (const float*)d_in[1];   // points_xyz_t: (B, 3, N)
    float* out = (float*)d_out;                   // (B, 3, NPOINT)

    // 48KB dynamic + ~0.5KB static smem -> opt-in. Host attribute call:
    // nothing enqueued, capture-safe, deterministic, idempotent.
    const int dyn_bytes = 3 * PER_CTA * (int)sizeof(float);   // 49152
    cudaFuncSetAttribute(fps_cluster_kernel,
                         cudaFuncAttributeMaxDynamicSharedMemorySize, dyn_bytes);

    fps_cluster_kernel<<<BATCH * CLUSTER, T, dyn_bytes>>>(xyz_t, out);
}

// round 10
// speedup vs baseline: 1.8620x; 1.8620x over previous
#include <cuda_runtime.h>
#include <cstdint>

// D-FPS (B=8, N=32768, npoint=2048) + gather xyz -> out (B,3,2048) fp32.
//
// One 8-CTA cluster per batch (64 CTAs, 256 threads = 8 warps). Each thread
// owns 16 points, PACKED f32x2 in registers; running-min temp in registers.
// Per iteration:
//   - packed add/mul.rn.f32x2 distance update (per-lane .rn => bit-exact)
//   - warp argmax via redux.sync (float bits of v>=0 are u32-monotone),
//     min-index tie-break == jnp.argmax first-occurrence
//   - CTA argmax in warp0 via redux over 8 warp candidates (lanes 0..7);
//     lanes 0..7 push {key,x,y,z} to cluster CTA dst==lane in parallel
//     (mapa + st.shared::cluster); winner coords from a CTA-local smem
//     coord table (LDS, not L2)
//   - ONE barrier.cluster (arrive releases the remote stores, wait acquires)
//   - every thread picks the cluster winner from its own smem slots.
// Fewer warps than the T=512 variant -> cheaper bar.sync drain and smaller
// cluster-barrier arrival spread at identical per-SMSP compute issue.
// Slots double-buffered by parity: a same-parity overwrite for iter j+2 can
// only be issued after the cluster barrier of iter j+1, which post-dates all
// reads of the iter-j slots.

constexpr int BATCH   = 8;
constexpr int NPTS    = 32768;
constexpr int NPOINT  = 2048;
constexpr int CLUSTER = 8;
constexpr int T       = 256;
constexpr int PER_CTA = NPTS / CLUSTER;  // 4096
constexpr int P       = PER_CTA / T;     // 16 points / thread
constexpr int NPAIR   = P / 2;           // 8 packed pairs
constexpr int NW      = T / 32;          // 8 warps

__device__ __forceinline__ uint32_t smem_u32(const void* p) {
    uint32_t a;
    asm("{ .reg .u64 t; cvta.to.shared.u64 t, %1; cvt.u32.u64 %0, t; }"
        : "=r"(a) : "l"(p));
    return a;
}

extern __shared__ float s_dyn[];  // sx[4096] | sy[4096] | sz[4096] = 48KB

__global__ __launch_bounds__(T, 1) __cluster_dims__(CLUSTER, 1, 1)
void fps_cluster_kernel(const float* __restrict__ xyz_t, float* __restrict__ out)
{
    const int b = blockIdx.x >> 3;
    uint32_t rank;
    asm("mov.u32 %0, %%cluster_ctarank;" : "=r"(rank));

    const float* __restrict__ xs = xyz_t + (size_t)b * 3 * NPTS;
    const float* __restrict__ ys = xs + NPTS;
    const float* __restrict__ zs = xs + 2 * NPTS;
    float* __restrict__ ob = out + (size_t)b * 3 * NPOINT;

    const int tid = threadIdx.x;
    const int w = tid >> 5, l = tid & 31;
    const int pbase = (int)rank * PER_CTA;

    float* sx = s_dyn;
    float* sy = s_dyn + PER_CTA;
    float* sz = s_dyn + 2 * PER_CTA;

    __shared__ uint32_t s_wv[NW], s_wi[NW];
    __shared__ unsigned long long s_key[2][CLUSTER];
    __shared__ float4 s_co[2][CLUSTER];

    // ---- load coords: smem table + packed registers ----
    unsigned long long xp[NPAIR], yp[NPAIR], zp[NPAIR];
    float tmp[P];
    {
        float a[P], c[P], d[P];
#pragma unroll
        for (int i = 0; i < P; ++i) {
            const int g = pbase + i * T + tid;
            a[i] = xs[g]; c[i] = ys[g]; d[i] = zs[g];
            sx[i * T + tid] = a[i];
            sy[i * T + tid] = c[i];
            sz[i * T + tid] = d[i];
            tmp[i] = 1e10f;
        }
#pragma unroll
        for (int q = 0; q < NPAIR; ++q) {
            asm("mov.b64 %0, {%1, %2};" : "=l"(xp[q]) : "f"(a[2*q]), "f"(a[2*q+1]));
            asm("mov.b64 %0, {%1, %2};" : "=l"(yp[q]) : "f"(c[2*q]), "f"(c[2*q+1]));
            asm("mov.b64 %0, {%1, %2};" : "=l"(zp[q]) : "f"(d[2*q]), "f"(d[2*q+1]));
        }
    }

    float lx = __ldg(xs), ly = __ldg(ys), lz = __ldg(zs);  // idx[0] = 0
    if (rank == 0 && tid == 0) {
        ob[0] = lx; ob[NPOINT] = ly; ob[2 * NPOINT] = lz;
    }

    for (int j = 1; j < NPOINT; ++j) {
        // packed negated center (per-lane duplicate)
        unsigned long long nlx2, nly2, nlz2;
        {
            const float nx = -lx, ny = -ly, nz = -lz;
            asm("mov.b64 %0, {%1, %1};" : "=l"(nlx2) : "f"(nx));
            asm("mov.b64 %0, {%1, %1};" : "=l"(nly2) : "f"(ny));
            asm("mov.b64 %0, {%1, %1};" : "=l"(nlz2) : "f"(nz));
        }

        float bv = -1.0f;
        int   bs = 0;
#pragma unroll
        for (int q = 0; q < NPAIR; ++q) {
            unsigned long long dx, dy, dz, qx, qy, qz, s01, acc;
            asm("add.rn.f32x2 %0, %1, %2;" : "=l"(dx) : "l"(xp[q]), "l"(nlx2));
            asm("add.rn.f32x2 %0, %1, %2;" : "=l"(dy) : "l"(yp[q]), "l"(nly2));
            asm("add.rn.f32x2 %0, %1, %2;" : "=l"(dz) : "l"(zp[q]), "l"(nlz2));
            asm("mul.rn.f32x2 %0, %1, %1;" : "=l"(qx) : "l"(dx));
            asm("mul.rn.f32x2 %0, %1, %1;" : "=l"(qy) : "l"(dy));
            asm("mul.rn.f32x2 %0, %1, %1;" : "=l"(qz) : "l"(dz));
            asm("add.rn.f32x2 %0, %1, %2;" : "=l"(s01) : "l"(qx), "l"(qy));
            asm("add.rn.f32x2 %0, %1, %2;" : "=l"(acc) : "l"(s01), "l"(qz));
            float d0, d1;
            asm("mov.b64 {%0, %1}, %2;" : "=f"(d0), "=f"(d1) : "l"(acc));
            float t0 = fminf(tmp[2*q], d0);     tmp[2*q] = t0;
            if (t0 > bv) { bv = t0; bs = 2*q; }
            float t1 = fminf(tmp[2*q+1], d1);   tmp[2*q+1] = t1;
            if (t1 > bv) { bv = t1; bs = 2*q+1; }
        }
        const uint32_t idx = (uint32_t)(pbase + bs * T + tid);

        // ---- warp argmax via redux (float bits of v>=0 are u32-monotone) ----
        const uint32_t vb   = __float_as_uint(bv);
        const uint32_t vmax = __reduce_max_sync(0xffffffffu, vb);
        const uint32_t imin = __reduce_min_sync(0xffffffffu,
                                   (vb == vmax) ? idx : 0xffffffffu);
        if (l == 0) { s_wv[w] = vmax; s_wi[w] = imin; }
        __syncthreads();

        const int p = j & 1;

        if (w == 0) {
            const uint32_t v  = (l < NW) ? s_wv[l] : 0u;
            const uint32_t ii = (l < NW) ? s_wi[l] : 0xffffffffu;
            const uint32_t vm = __reduce_max_sync(0xffffffffu, v);
            const uint32_t im = __reduce_min_sync(0xffffffffu,
                                    (v == vm) ? ii : 0xffffffffu);
            // redux leaves the result in every lane: lanes 0..7 disseminate
            // to cluster CTA dst == lane, in parallel.
            if (l < CLUSTER) {
                const int li = (int)im - pbase;      // winner is in own range
                const float cx = sx[li], cy = sy[li], cz = sz[li];  // LDS bcast
                const unsigned long long key =
                    ((unsigned long long)vm << 32) | (uint32_t)(~im);
                unsigned long long xyp;
                asm("mov.b64 %0, {%1, %2};" : "=l"(xyp) : "f"(cx), "f"(cy));
                const uint32_t zb = __float_as_uint(cz);
                const uint32_t ka = smem_u32(&s_key[p][rank]);
                const uint32_t ca = smem_u32(&s_co[p][rank]);
                const int dco = (int)(ca - ka);
                uint32_t rk;
                asm volatile("mapa.shared::cluster.u32 %0, %1, %2;"
                             : "=r"(rk) : "r"(ka), "r"(l));
                asm volatile("st.shared::cluster.b64 [%0], %1;"
                             :: "r"(rk), "l"(key) : "memory");
                asm volatile("st.shared::cluster.b64 [%0], %1;"
                             :: "r"(rk + dco), "l"(xyp) : "memory");
                asm volatile("st.shared::cluster.b32 [%0+8], %1;"
                             :: "r"(rk + dco), "r"(zb) : "memory");
            }
        }

        // arrive = release (orders the shared::cluster stores), wait = acquire
        asm volatile("barrier.cluster.arrive.aligned;" ::: "memory");
        asm volatile("barrier.cluster.wait.aligned;" ::: "memory");

        // ---- every thread picks the cluster winner locally ----
        unsigned long long wk = s_key[p][0];
        int wc = 0;
#pragma unroll
        for (int c = 1; c < CLUSTER; ++c) {
            const unsigned long long kk = s_key[p][c];
            if (kk > wk) { wk = kk; wc = c; }
        }
        const float4 co = s_co[p][wc];
        lx = co.x; ly = co.y; lz = co.z;

        if (rank == 0 && tid == 0) {
            ob[j]              = lx;
            ob[NPOINT + j]     = ly;
            ob[2 * NPOINT + j] = lz;
        }
    }
}

extern "C" void kernel_launch(void* const* d_in, const int* in_sizes, int n_in,
                              void* d_out, int out_size)
{
    (void)in_sizes; (void)n_in; (void)out_size;
    const float* xyz_t = (const float*)d_in[1];   // points_xyz_t: (B, 3, N)
    float* out = (float*)d_out;                   // (B, 3, NPOINT)

    // Opt in to >48KB-total smem (48KB dynamic + ~0.3KB static). Host-side
    // attribute call: nothing enqueued on the stream, capture-safe,
    // deterministic and idempotent.
    const int dyn_bytes = 3 * PER_CTA * (int)sizeof(float);   // 49152
    cudaFuncSetAttribute(fps_cluster_kernel,
                         cudaFuncAttributeMaxDynamicSharedMemorySize, dyn_bytes);

    fps_cluster_kernel<<<BATCH * CLUSTER, T, dyn_bytes>>>(xyz_t, out);
}

// round 11
// speedup vs baseline: 1.9966x; 1.0723x over previous
#include <cuda_runtime.h>
#include <cstdint>

// D-FPS (B=8, N=32768, npoint=2048) + gather xyz -> out (B,3,2048) fp32.
//
// One 8-CTA cluster per batch (64 CTAs, 128 threads = 4 warps). Each thread
// owns 32 points, PACKED f32x2 in registers; running-min temp in registers.
// Per iteration:
//   - packed add/mul.rn.f32x2 distance update (per-lane .rn => bit-exact)
//   - warp argmax via redux.sync (float bits of v>=0 are u32-monotone),
//     min-index tie-break == jnp.argmax first-occurrence
//   - CTA argmax in warp0 via redux over 4 warp candidates (lanes 0..3);
//     lanes 0..7 push {key,x,y,z} to cluster CTA dst==lane in parallel
//     (mapa + st.shared::cluster); winner coords from a CTA-local smem
//     coord table (LDS, not L2)
//   - ONE barrier.cluster (arrive releases the remote stores, wait acquires)
//   - every thread picks the cluster winner from its own smem slots.
// Fewer warps -> cheaper bar.sync drain, smaller cluster-barrier arrival
// spread, shorter post-barrier tail, at unchanged per-SMSP compute issue
// (ILP from 16 independent packed pairs covers the 4-cyc fma latency).
// Slots double-buffered by parity: a same-parity overwrite for iter j+2 can
// only be issued after the cluster barrier of iter j+1, which post-dates all
// reads of the iter-j slots.

constexpr int BATCH   = 8;
constexpr int NPTS    = 32768;
constexpr int NPOINT  = 2048;
constexpr int CLUSTER = 8;
constexpr int T       = 128;
constexpr int PER_CTA = NPTS / CLUSTER;  // 4096
constexpr int P       = PER_CTA / T;     // 32 points / thread
constexpr int NPAIR   = P / 2;           // 16 packed pairs
constexpr int NW      = T / 32;          // 4 warps

__device__ __forceinline__ uint32_t smem_u32(const void* p) {
    uint32_t a;
    asm("{ .reg .u64 t; cvta.to.shared.u64 t, %1; cvt.u32.u64 %0, t; }"
        : "=r"(a) : "l"(p));
    return a;
}

extern __shared__ float s_dyn[];  // sx[4096] | sy[4096] | sz[4096] = 48KB

__global__ __launch_bounds__(T, 1) __cluster_dims__(CLUSTER, 1, 1)
void fps_cluster_kernel(const float* __restrict__ xyz_t, float* __restrict__ out)
{
    const int b = blockIdx.x >> 3;
    uint32_t rank;
    asm("mov.u32 %0, %%cluster_ctarank;" : "=r"(rank));

    const float* __restrict__ xs = xyz_t + (size_t)b * 3 * NPTS;
    const float* __restrict__ ys = xs + NPTS;
    const float* __restrict__ zs = xs + 2 * NPTS;
    float* __restrict__ ob = out + (size_t)b * 3 * NPOINT;

    const int tid = threadIdx.x;
    const int w = tid >> 5, l = tid & 31;
    const int pbase = (int)rank * PER_CTA;

    float* sx = s_dyn;
    float* sy = s_dyn + PER_CTA;
    float* sz = s_dyn + 2 * PER_CTA;

    __shared__ uint32_t s_wv[NW], s_wi[NW];
    __shared__ unsigned long long s_key[2][CLUSTER];
    __shared__ float4 s_co[2][CLUSTER];

    // ---- load coords: smem table + packed registers ----
    unsigned long long xp[NPAIR], yp[NPAIR], zp[NPAIR];
    float tmp[P];
#pragma unroll
    for (int q = 0; q < NPAIR; ++q) {
        const int g0 = pbase + (2 * q)     * T + tid;
        const int g1 = pbase + (2 * q + 1) * T + tid;
        const float ax0 = xs[g0], ax1 = xs[g1];
        const float ay0 = ys[g0], ay1 = ys[g1];
        const float az0 = zs[g0], az1 = zs[g1];
        sx[(2*q)   * T + tid] = ax0;  sx[(2*q+1) * T + tid] = ax1;
        sy[(2*q)   * T + tid] = ay0;  sy[(2*q+1) * T + tid] = ay1;
        sz[(2*q)   * T + tid] = az0;  sz[(2*q+1) * T + tid] = az1;
        asm("mov.b64 %0, {%1, %2};" : "=l"(xp[q]) : "f"(ax0), "f"(ax1));
        asm("mov.b64 %0, {%1, %2};" : "=l"(yp[q]) : "f"(ay0), "f"(ay1));
        asm("mov.b64 %0, {%1, %2};" : "=l"(zp[q]) : "f"(az0), "f"(az1));
        tmp[2*q] = 1e10f; tmp[2*q+1] = 1e10f;
    }

    float lx = __ldg(xs), ly = __ldg(ys), lz = __ldg(zs);  // idx[0] = 0
    if (rank == 0 && tid == 0) {
        ob[0] = lx; ob[NPOINT] = ly; ob[2 * NPOINT] = lz;
    }

    for (int j = 1; j < NPOINT; ++j) {
        // packed negated center (per-lane duplicate)
        unsigned long long nlx2, nly2, nlz2;
        {
            const float nx = -lx, ny = -ly, nz = -lz;
            asm("mov.b64 %0, {%1, %1};" : "=l"(nlx2) : "f"(nx));
            asm("mov.b64 %0, {%1, %1};" : "=l"(nly2) : "f"(ny));
            asm("mov.b64 %0, {%1, %1};" : "=l"(nlz2) : "f"(nz));
        }

        float bv = -1.0f;
        int   bs = 0;
#pragma unroll
        for (int q = 0; q < NPAIR; ++q) {
            unsigned long long dx, dy, dz, qx, qy, qz, s01, acc;
            asm("add.rn.f32x2 %0, %1, %2;" : "=l"(dx) : "l"(xp[q]), "l"(nlx2));
            asm("add.rn.f32x2 %0, %1, %2;" : "=l"(dy) : "l"(yp[q]), "l"(nly2));
            asm("add.rn.f32x2 %0, %1, %2;" : "=l"(dz) : "l"(zp[q]), "l"(nlz2));
            asm("mul.rn.f32x2 %0, %1, %1;" : "=l"(qx) : "l"(dx));
            asm("mul.rn.f32x2 %0, %1, %1;" : "=l"(qy) : "l"(dy));
            asm("mul.rn.f32x2 %0, %1, %1;" : "=l"(qz) : "l"(dz));
            asm("add.rn.f32x2 %0, %1, %2;" : "=l"(s01) : "l"(qx), "l"(qy));
            asm("add.rn.f32x2 %0, %1, %2;" : "=l"(acc) : "l"(s01), "l"(qz));
            float d0, d1;
            asm("mov.b64 {%0, %1}, %2;" : "=f"(d0), "=f"(d1) : "l"(acc));
            float t0 = fminf(tmp[2*q], d0);     tmp[2*q] = t0;
            if (t0 > bv) { bv = t0; bs = 2*q; }
            float t1 = fminf(tmp[2*q+1], d1);   tmp[2*q+1] = t1;
            if (t1 > bv) { bv = t1; bs = 2*q+1; }
        }
        const uint32_t idx = (uint32_t)(pbase + bs * T + tid);

        // ---- warp argmax via redux (float bits of v>=0 are u32-monotone) ----
        const uint32_t vb   = __float_as_uint(bv);
        const uint32_t vmax = __reduce_max_sync(0xffffffffu, vb);
        const uint32_t imin = __reduce_min_sync(0xffffffffu,
                                   (vb == vmax) ? idx : 0xffffffffu);
        if (l == 0) { s_wv[w] = vmax; s_wi[w] = imin; }
        __syncthreads();

        const int p = j & 1;

        if (w == 0) {
            const uint32_t v  = (l < NW) ? s_wv[l] : 0u;
            const uint32_t ii = (l < NW) ? s_wi[l] : 0xffffffffu;
            const uint32_t vm = __reduce_max_sync(0xffffffffu, v);
            const uint32_t im = __reduce_min_sync(0xffffffffu,
                                    (v == vm) ? ii : 0xffffffffu);
            // redux leaves the result in every lane: lanes 0..7 disseminate
            // to cluster CTA dst == lane, in parallel.
            if (l < CLUSTER) {
                const int li = (int)im - pbase;      // winner is in own range
                const float cx = sx[li], cy = sy[li], cz = sz[li];  // LDS bcast
                const unsigned long long key =
                    ((unsigned long long)vm << 32) | (uint32_t)(~im);
                unsigned long long xyp;
                asm("mov.b64 %0, {%1, %2};" : "=l"(xyp) : "f"(cx), "f"(cy));
                const uint32_t zb = __float_as_uint(cz);
                const uint32_t ka = smem_u32(&s_key[p][rank]);
                const uint32_t ca = smem_u32(&s_co[p][rank]);
                const int dco = (int)(ca - ka);
                uint32_t rk;
                asm volatile("mapa.shared::cluster.u32 %0, %1, %2;"
                             : "=r"(rk) : "r"(ka), "r"(l));
                asm volatile("st.shared::cluster.b64 [%0], %1;"
                             :: "r"(rk), "l"(key) : "memory");
                asm volatile("st.shared::cluster.b64 [%0], %1;"
                             :: "r"(rk + dco), "l"(xyp) : "memory");
                asm volatile("st.shared::cluster.b32 [%0+8], %1;"
                             :: "r"(rk + dco), "r"(zb) : "memory");
            }
        }

        // arrive = release (orders the shared::cluster stores), wait = acquire
        asm volatile("barrier.cluster.arrive.aligned;" ::: "memory");
        asm volatile("barrier.cluster.wait.aligned;" ::: "memory");

        // ---- every thread picks the cluster winner locally ----
        unsigned long long wk = s_key[p][0];
        int wc = 0;
#pragma unroll
        for (int c = 1; c < CLUSTER; ++c) {
            const unsigned long long kk = s_key[p][c];
            if (kk > wk) { wk = kk; wc = c; }
        }
        const float4 co = s_co[p][wc];
        lx = co.x; ly = co.y; lz = co.z;

        if (rank == 0 && tid == 0) {
            ob[j]              = lx;
            ob[NPOINT + j]     = ly;
            ob[2 * NPOINT + j] = lz;
        }
    }
}

extern "C" void kernel_launch(void* const* d_in, const int* in_sizes, int n_in,
                              void* d_out, int out_size)
{
    (void)in_sizes; (void)n_in; (void)out_size;
    const float* xyz_t = (const float*)d_in[1];   // points_xyz_t: (B, 3, N)
    float* out = (float*)d_out;                   // (B, 3, NPOINT)

    // Opt in to >48KB-total smem (48KB dynamic + ~0.3KB static). Host-side
    // attribute call: nothing enqueued on the stream, capture-safe,
    // deterministic and idempotent.
    const int dyn_bytes = 3 * PER_CTA * (int)sizeof(float);   // 49152
    cudaFuncSetAttribute(fps_cluster_kernel,
                         cudaFuncAttributeMaxDynamicSharedMemorySize, dyn_bytes);

    fps_cluster_kernel<<<BATCH * CLUSTER, T, dyn_bytes>>>(xyz_t, out);
}